// round 10
// baseline (speedup 1.0000x reference)
#include <cuda_runtime.h>
#include <math.h>

#define T_STEPS 2048
#define BATCH   64
#define IN_DIM  27
#define H1      400
#define H2      200
#define NGROUP  4            // independent batch groups of 16
#define GPC     37           // CTAs per group (4*37 = 148 SMs)
#define K4      (H1 / 4)

// ---------------- device scratch (static; zero-init) ----------------
// g_xw[t][row(1600)][b] : x@W_ih^T + b_ih + b_hh
static __device__ float g_xw[(size_t)T_STEPS * 4 * H1 * BATCH];
// g_hr group-blocked: [t][g][k>>2][b16][k&3]; t=0 slot = h_{-1} = 0
static __device__ float g_hr[(size_t)(T_STEPS + 1) * H1 * BATCH];
static __device__ unsigned int g_bars[128];   // group g counter @ g*32 (128B apart)

__device__ __forceinline__ void ffma2(unsigned long long &acc,
                                      unsigned long long a, unsigned long long b) {
    asm("fma.rn.f32x2 %0, %1, %2, %0;" : "+l"(acc) : "l"(a), "l"(b));
}
__device__ __forceinline__ float lo32(unsigned long long v) { return __uint_as_float((unsigned)v); }
__device__ __forceinline__ float hi32(unsigned long long v) { return __uint_as_float((unsigned)(v >> 32)); }

__device__ __forceinline__ void cp16(float* smem_dst, const float* gmem_src) {
    unsigned saddr = (unsigned)__cvta_generic_to_shared(smem_dst);
    asm volatile("cp.async.cg.shared.global [%0], [%1], 16;" :: "r"(saddr), "l"(gmem_src));
}

// =====================================================================
// Kernel 1: xw[t][r][b] = word[t,b,:] . W_ih[r,:] + b_ih[r] + b_hh[r]
// grid (25, 2048), block 256. Resets group barrier counters.
// =====================================================================
__global__ void __launch_bounds__(256) k_xw(const float* __restrict__ word,
                                            const float* __restrict__ Wih,
                                            const float* __restrict__ bih,
                                            const float* __restrict__ bhh) {
    __shared__ float xs[IN_DIM * 68];
    __shared__ float ws[64 * 28];
    __shared__ float bs[64];
    const int t = blockIdx.y;
    const int rbase = blockIdx.x * 64;
    const int tid = threadIdx.x;

    if (blockIdx.x == 0 && blockIdx.y == 0 && tid < 128) g_bars[tid] = 0u;

    for (int j = tid; j < BATCH * IN_DIM; j += 256) {
        int b = j / IN_DIM, i = j - b * IN_DIM;
        xs[i * 68 + b] = word[(size_t)t * (BATCH * IN_DIM) + j];
    }
    for (int j = tid; j < 64 * IN_DIM; j += 256) {
        int r = j / IN_DIM, i = j - r * IN_DIM;
        ws[r * 28 + i] = Wih[(size_t)(rbase + r) * IN_DIM + i];
    }
    if (tid < 64) bs[tid] = bih[rbase + tid] + bhh[rbase + tid];
    __syncthreads();

    const int rq = tid >> 4;
    const int bq = (tid & 15) * 4;
    float acc[4][4];
    #pragma unroll
    for (int r = 0; r < 4; r++) {
        float bv = bs[rq * 4 + r];
        #pragma unroll
        for (int b = 0; b < 4; b++) acc[r][b] = bv;
    }
    #pragma unroll 3
    for (int i = 0; i < IN_DIM; i++) {
        float4 xv = *(const float4*)&xs[i * 68 + bq];
        #pragma unroll
        for (int r = 0; r < 4; r++) {
            float w = ws[(rq * 4 + r) * 28 + i];
            acc[r][0] += w * xv.x; acc[r][1] += w * xv.y;
            acc[r][2] += w * xv.z; acc[r][3] += w * xv.w;
        }
    }
    size_t base = ((size_t)t * (4 * H1) + rbase) * BATCH;
    #pragma unroll
    for (int r = 0; r < 4; r++) {
        float4 v = make_float4(acc[r][0], acc[r][1], acc[r][2], acc[r][3]);
        *(float4*)&g_xw[base + (size_t)(rq * 4 + r) * BATCH + bq] = v;
    }
}

// =====================================================================
// Kernel 2: recurrence. 4 independent groups x 37 CTAs, block 256.
// Thread (rslot 0..15, b16 0..15): rows rslot, rslot+16, rslot+32 (<R),
// one batch, all 400 k. No k-split -> 3 accumulators, no reduction.
// dyn smem: hs[6400] | ws[R<=44][400] | gb[44][16]
// =====================================================================
#define HSG_F 6400
#define WSG_F (44 * H1)
#define GBG_F 768
#define REC_SMEM_B ((HSG_F + WSG_F + GBG_F) * 4)

template<int NU>
__device__ __forceinline__ void rec_body(const float* __restrict__ Whh,
                                         int group, int u0,
                                         float* hs, float* ws, float* gb) {
    constexpr int R = 4 * NU;
    const int tid   = threadIdx.x;
    const int b16   = tid & 15;
    const int rslot = tid >> 4;
    const bool has3 = (rslot + 32 < R);

    // stage W_hh slice: ws[row][k], row = gate*NU + q -> global gate*H1+u0+q
    for (int idx = tid; idx < R * H1; idx += 256) {
        int row = idx / H1, k = idx - row * H1;
        int gate = row / NU, q = row - gate * NU;
        ws[row * H1 + k] = Whh[(size_t)(gate * H1 + u0 + q) * H1 + k];
    }

    // combine mapping: unit cq = rslot (active < NU), batch b16
    const int cq  = rslot;
    const int uu  = u0 + (cq < NU ? cq : 0);
    const int cbg = group * 16 + b16;
    const size_t hr_off = (size_t)group * HSG_F + (size_t)(uu >> 2) * 64 + b16 * 4 + (uu & 3);
    float c_val = 0.0f;
    unsigned int* bar = &g_bars[group * 32];

    __syncthreads();

    // prefetch xw for step 0
    float xw0 = 0.f, xw1 = 0.f, xw2 = 0.f, xw3 = 0.f;
    if (cq < NU) {
        const float* xp = g_xw;
        xw0 = __ldcg(&xp[(size_t)(0 * H1 + uu) * BATCH + cbg]);
        xw1 = __ldcg(&xp[(size_t)(1 * H1 + uu) * BATCH + cbg]);
        xw2 = __ldcg(&xp[(size_t)(2 * H1 + uu) * BATCH + cbg]);
        xw3 = __ldcg(&xp[(size_t)(3 * H1 + uu) * BATCH + cbg]);
    }

    for (int t = 0; t < T_STEPS; t++) {
        // ---- stage this group's h slice (25.6KB) into smem ----
        {
            const float* hb = g_hr + (size_t)t * (H1 * BATCH) + group * HSG_F;
            #pragma unroll
            for (int i = 0; i < 7; i++) {
                int e = tid + i * 256;
                if (e < 1600) cp16(&hs[e * 4], hb + e * 4);
            }
            asm volatile("cp.async.commit_group;");
            asm volatile("cp.async.wait_group 0;");
        }
        __syncthreads();

        // ---- dots: up to 3 rows x 1 batch over all 400 k ----
        unsigned long long a0 = 0ull, a1 = 0ull, a2 = 0ull;
        const float* w0p = &ws[(rslot +  0) * H1];
        const float* w1p = &ws[(rslot + 16) * H1];
        const float* w2p = &ws[(rslot + 32 < R ? rslot + 32 : rslot) * H1];
        #pragma unroll 4
        for (int k4 = 0; k4 < K4; k4++) {
            ulonglong2 h4 = *(const ulonglong2*)&hs[k4 * 64 + b16 * 4];
            ulonglong2 w2a = *(const ulonglong2*)&w0p[k4 * 4];
            ffma2(a0, h4.x, w2a.x); ffma2(a0, h4.y, w2a.y);
            ulonglong2 w2b = *(const ulonglong2*)&w1p[k4 * 4];
            ffma2(a1, h4.x, w2b.x); ffma2(a1, h4.y, w2b.y);
            if (has3) {
                ulonglong2 w2c = *(const ulonglong2*)&w2p[k4 * 4];
                ffma2(a2, h4.x, w2c.x); ffma2(a2, h4.y, w2c.y);
            }
        }
        gb[(rslot +  0) * 16 + b16] = lo32(a0) + hi32(a0);
        gb[(rslot + 16) * 16 + b16] = lo32(a1) + hi32(a1);
        if (has3) gb[(rslot + 32) * 16 + b16] = lo32(a2) + hi32(a2);
        __syncthreads();

        // ---- combine: LSTM cell for (unit uu, batch cbg) ----
        if (cq < NU) {
            float g0 = xw0 + gb[(0 * NU + cq) * 16 + b16];
            float g1 = xw1 + gb[(1 * NU + cq) * 16 + b16];
            float g2 = xw2 + gb[(2 * NU + cq) * 16 + b16];
            float g3 = xw3 + gb[(3 * NU + cq) * 16 + b16];
            float iv = 1.0f / (1.0f + expf(-g0));
            float fv = 1.0f / (1.0f + expf(-g1));
            float gv = tanhf(g2);
            float ov = 1.0f / (1.0f + expf(-g3));
            float cn = fv * c_val + iv * gv;
            float hn = ov * tanhf(cn);
            c_val = fmaxf(cn, 0.0f);
            g_hr[(size_t)(t + 1) * (H1 * BATCH) + hr_off] = fmaxf(hn, 0.0f);
        }

        // ---- prefetch xw for t+1 (hidden under barrier) ----
        if (cq < NU && t + 1 < T_STEPS) {
            const float* xp = g_xw + (size_t)(t + 1) * (4 * H1) * BATCH;
            xw0 = __ldcg(&xp[(size_t)(0 * H1 + uu) * BATCH + cbg]);
            xw1 = __ldcg(&xp[(size_t)(1 * H1 + uu) * BATCH + cbg]);
            xw2 = __ldcg(&xp[(size_t)(2 * H1 + uu) * BATCH + cbg]);
            xw3 = __ldcg(&xp[(size_t)(3 * H1 + uu) * BATCH + cbg]);
        }

        // ---- group barrier (R4-proven shape, 37 arrivals) ----
        __threadfence();
        __syncthreads();
        if (tid == 0) {
            atomicAdd(bar, 1u);
            const unsigned target = (unsigned)(t + 1) * GPC;
            unsigned v;
            do {
                asm volatile("ld.acquire.gpu.u32 %0, [%1];" : "=r"(v) : "l"(bar));
            } while (v < target);
        }
        __syncthreads();
    }
}

__global__ void __launch_bounds__(256, 1) k_rec(const float* __restrict__ Whh) {
    extern __shared__ float sm[];
    float* hs = sm;
    float* ws = sm + HSG_F;
    float* gb = sm + HSG_F + WSG_F;
    const int bid   = blockIdx.x;
    const int group = bid / GPC;
    const int rank  = bid - group * GPC;
    // 30 CTAs x 11 units + 7 CTAs x 10 units = 400 units
    if (rank < 30) rec_body<11>(Whh, group, rank * 11, hs, ws, gb);
    else           rec_body<10>(Whh, group, 330 + (rank - 30) * 10, hs, ws, gb);
}

// =====================================================================
// Kernel 3: MLP head per timestep (group-blocked h layout). grid 2048.
// =====================================================================
#define HS_F 25600
#define HEAD_SMEM_B ((HS_F + H2 * BATCH) * 4)

__global__ void __launch_bounds__(256) k_head(const float* __restrict__ Wfc,
                                              const float* __restrict__ bfc,
                                              const float* __restrict__ Wout,
                                              const float* __restrict__ bout,
                                              float* __restrict__ out) {
    extern __shared__ float sm[];
    float* hs  = sm;
    float* hid = sm + HS_F;
    const int t = blockIdx.x;
    const int tid = threadIdx.x;

    const float4* hsrc = (const float4*)(g_hr + (size_t)(t + 1) * (H1 * BATCH));
    for (int i = tid; i < (H1 * BATCH) / 4; i += 256)
        ((float4*)hs)[i] = hsrc[i];
    __syncthreads();

    const int jrow = tid >> 4;
    const int bq   = (tid & 15) * 4;          // batches bq..bq+3, same group
    const int gblk = (bq >> 4) * HSG_F;       // group slice base
    const int b16  = bq & 15;
    for (int j = jrow; j < H2; j += 16) {
        float bv = bfc[j];
        float4 acc = make_float4(bv, bv, bv, bv);
        const float4* wr = (const float4*)(Wfc + (size_t)j * H1);
        #pragma unroll 4
        for (int k4 = 0; k4 < K4; k4++) {
            float4 w4 = wr[k4];
            float4 h0 = *(const float4*)&hs[gblk + k4 * 64 + (b16 + 0) * 4];
            float4 h1 = *(const float4*)&hs[gblk + k4 * 64 + (b16 + 1) * 4];
            float4 h2 = *(const float4*)&hs[gblk + k4 * 64 + (b16 + 2) * 4];
            float4 h3 = *(const float4*)&hs[gblk + k4 * 64 + (b16 + 3) * 4];
            acc.x += w4.x * h0.x + w4.y * h0.y + w4.z * h0.z + w4.w * h0.w;
            acc.y += w4.x * h1.x + w4.y * h1.y + w4.z * h1.z + w4.w * h1.w;
            acc.z += w4.x * h2.x + w4.y * h2.y + w4.z * h2.z + w4.w * h2.w;
            acc.w += w4.x * h3.x + w4.y * h3.y + w4.z * h3.z + w4.w * h3.w;
        }
        acc.x = fmaxf(acc.x, 0.f); acc.y = fmaxf(acc.y, 0.f);
        acc.z = fmaxf(acc.z, 0.f); acc.w = fmaxf(acc.w, 0.f);
        *(float4*)&hid[j * BATCH + bq] = acc;
    }
    __syncthreads();

    if (tid < BATCH) {
        float s = bout[0];
        #pragma unroll 8
        for (int j = 0; j < H2; j++)
            s += hid[j * BATCH + tid] * Wout[j];
        out[(size_t)t * BATCH + tid] = 1.0f / (1.0f + expf(-s));
    }
}

// =====================================================================
extern "C" void kernel_launch(void* const* d_in, const int* in_sizes, int n_in,
                              void* d_out, int out_size) {
    const float* word = (const float*)d_in[0];
    const float* Wih  = (const float*)d_in[1];
    const float* Whh  = (const float*)d_in[2];
    const float* bih  = (const float*)d_in[3];
    const float* bhh  = (const float*)d_in[4];
    const float* Wfc  = (const float*)d_in[5];
    const float* bfc  = (const float*)d_in[6];
    const float* Wout = (const float*)d_in[7];
    const float* bout = (const float*)d_in[8];
    float* out = (float*)d_out;

    cudaFuncSetAttribute(k_rec,  cudaFuncAttributeMaxDynamicSharedMemorySize, REC_SMEM_B);
    cudaFuncSetAttribute(k_head, cudaFuncAttributeMaxDynamicSharedMemorySize, HEAD_SMEM_B);

    k_xw<<<dim3(25, T_STEPS), 256>>>(word, Wih, bih, bhh);
    k_rec<<<NGROUP * GPC, 256, REC_SMEM_B>>>(Whh);
    k_head<<<T_STEPS, 256, HEAD_SMEM_B>>>(Wfc, bfc, Wout, bout, out);
}